// round 1
// baseline (speedup 1.0000x reference)
#include <cuda_runtime.h>
#include <cstdint>

// Problem constants
#define B 4
#define N 4096
#define D 1024
#define ROWS (B * N)          // 16384
#define SCALE 0.03125f        // 1/sqrt(1024)

// Scratch (device globals — no allocations allowed)
__device__ float g_Q[(size_t)ROWS * D];       // 64 MB
__device__ float g_K[(size_t)ROWS * D];       // 64 MB
__device__ float g_L[(size_t)B * N * N];      // 256 MB
__device__ float g_vmean[ROWS];
__device__ float g_wvbar[D];

// ---------------------------------------------------------------------------
// wvbar[e] = mean_d Wv[e, d]   (one warp per row)
// ---------------------------------------------------------------------------
__global__ void wvbar_kernel(const float* __restrict__ Wv) {
    int row = blockIdx.x * (blockDim.x >> 5) + (threadIdx.x >> 5);
    int lane = threadIdx.x & 31;
    if (row >= D) return;
    const float* p = Wv + (size_t)row * D;
    float s = 0.f;
    #pragma unroll 4
    for (int j = lane; j < D; j += 32) s += p[j];
    #pragma unroll
    for (int o = 16; o > 0; o >>= 1) s += __shfl_xor_sync(0xffffffffu, s, o);
    if (lane == 0) g_wvbar[row] = s * (1.0f / (float)D);
}

// ---------------------------------------------------------------------------
// vmean[r] = X[r, :] . wvbar    (one warp per row, float4 loads)
// ---------------------------------------------------------------------------
__global__ void vmean_kernel(const float* __restrict__ X) {
    int row = blockIdx.x * (blockDim.x >> 5) + (threadIdx.x >> 5);
    int lane = threadIdx.x & 31;
    if (row >= ROWS) return;
    const float4* p = (const float4*)(X + (size_t)row * D);
    const float4* w = (const float4*)g_wvbar;
    float s = 0.f;
    #pragma unroll 8
    for (int j = lane; j < D / 4; j += 32) {
        float4 a = p[j], b = w[j];
        s += a.x * b.x + a.y * b.y + a.z * b.z + a.w * b.w;
    }
    #pragma unroll
    for (int o = 16; o > 0; o >>= 1) s += __shfl_xor_sync(0xffffffffu, s, o);
    if (lane == 0) g_vmean[row] = s;
}

// ---------------------------------------------------------------------------
// SGEMM NN: C[M,Nn] = A[M,K] * Bm[K,Nn], all row-major.
// 128x128 tile, BK=8, 256 threads, 8x8 per thread.
// M=16384, Nn=1024, K=1024 (all divisible; no bounds checks)
// ---------------------------------------------------------------------------
#define BM 128
#define BN 128
#define BK 8
#define TM 8
#define TN 8

__global__ __launch_bounds__(256)
void sgemm_nn(const float* __restrict__ A, const float* __restrict__ Bm,
              float* __restrict__ C, int M, int Nn, int K) {
    __shared__ float As[BK][BM];
    __shared__ float Bs[BK][BN];
    const int tid = threadIdx.x;
    const int bx = blockIdx.x;   // N tile
    const int by = blockIdx.y;   // M tile
    const int tcol = tid & 15;   // 16 thread cols
    const int trow = tid >> 4;   // 16 thread rows

    const int aRow = tid >> 1, aCol = (tid & 1) * 4;        // 128x8 via float4
    const int bRow = tid >> 5, bCol = (tid & 31) * 4;       // 8x128 via float4

    const float* Ap = A + (size_t)(by * BM + aRow) * K + aCol;
    const float* Bp = Bm + (size_t)bRow * Nn + bx * BN + bCol;

    float acc[TM][TN] = {};
    float ra[TM], rb[TN];

    for (int k0 = 0; k0 < K; k0 += BK) {
        float4 av = *(const float4*)Ap;  Ap += BK;
        float4 bv = *(const float4*)Bp;  Bp += (size_t)BK * Nn;
        As[aCol + 0][aRow] = av.x;
        As[aCol + 1][aRow] = av.y;
        As[aCol + 2][aRow] = av.z;
        As[aCol + 3][aRow] = av.w;
        *(float4*)&Bs[bRow][bCol] = bv;
        __syncthreads();
        #pragma unroll
        for (int k = 0; k < BK; k++) {
            #pragma unroll
            for (int i = 0; i < TM; i++) ra[i] = As[k][trow * TM + i];
            #pragma unroll
            for (int j = 0; j < TN; j++) rb[j] = Bs[k][tcol * TN + j];
            #pragma unroll
            for (int i = 0; i < TM; i++)
                #pragma unroll
                for (int j = 0; j < TN; j++) acc[i][j] += ra[i] * rb[j];
        }
        __syncthreads();
    }

    float* Cp = C + (size_t)(by * BM + trow * TM) * Nn + bx * BN + tcol * TN;
    #pragma unroll
    for (int i = 0; i < TM; i++) {
        #pragma unroll
        for (int j = 0; j < TN; j += 4) {
            float4 v = make_float4(acc[i][j], acc[i][j+1], acc[i][j+2], acc[i][j+3]);
            *(float4*)(Cp + (size_t)i * Nn + j) = v;
        }
    }
}

// ---------------------------------------------------------------------------
// Batched NT GEMM: L[b][n,m] = SCALE * sum_d Q[b,n,d] * K[b,m,d]
// Per batch: 4096x4096x1024. blockIdx.z = batch.
// ---------------------------------------------------------------------------
__global__ __launch_bounds__(256)
void logits_nt(void) {
    const int b = blockIdx.z;
    const float* A = g_Q + (size_t)b * N * D;
    const float* Bp0 = g_K + (size_t)b * N * D;
    float* C = g_L + (size_t)b * N * N;

    __shared__ float As[BK][BM];
    __shared__ float Bs[BK][BN];
    const int tid = threadIdx.x;
    const int bx = blockIdx.x;   // m tile (cols)
    const int by = blockIdx.y;   // n tile (rows)
    const int tcol = tid & 15;
    const int trow = tid >> 4;

    const int aRow = tid >> 1, aCol = (tid & 1) * 4;  // both tiles are 128 rows x 8 k

    const float* Ap = A + (size_t)(by * BM + aRow) * D + aCol;
    const float* Bp = Bp0 + (size_t)(bx * BN + aRow) * D + aCol;

    float acc[TM][TN] = {};
    float ra[TM], rb[TN];

    for (int k0 = 0; k0 < D; k0 += BK) {
        float4 av = *(const float4*)Ap;  Ap += BK;
        float4 bv = *(const float4*)Bp;  Bp += BK;
        As[aCol + 0][aRow] = av.x;
        As[aCol + 1][aRow] = av.y;
        As[aCol + 2][aRow] = av.z;
        As[aCol + 3][aRow] = av.w;
        Bs[aCol + 0][aRow] = bv.x;
        Bs[aCol + 1][aRow] = bv.y;
        Bs[aCol + 2][aRow] = bv.z;
        Bs[aCol + 3][aRow] = bv.w;
        __syncthreads();
        #pragma unroll
        for (int k = 0; k < BK; k++) {
            #pragma unroll
            for (int i = 0; i < TM; i++) ra[i] = As[k][trow * TM + i];
            #pragma unroll
            for (int j = 0; j < TN; j++) rb[j] = Bs[k][tcol * TN + j];
            #pragma unroll
            for (int i = 0; i < TM; i++)
                #pragma unroll
                for (int j = 0; j < TN; j++) acc[i][j] += ra[i] * rb[j];
        }
        __syncthreads();
    }

    float* Cp = C + (size_t)(by * BM + trow * TM) * N + bx * BN + tcol * TN;
    #pragma unroll
    for (int i = 0; i < TM; i++) {
        #pragma unroll
        for (int j = 0; j < TN; j += 4) {
            float4 v = make_float4(acc[i][j] * SCALE, acc[i][j+1] * SCALE,
                                   acc[i][j+2] * SCALE, acc[i][j+3] * SCALE);
            *(float4*)(Cp + (size_t)i * N + j) = v;
        }
    }
}

// ---------------------------------------------------------------------------
// Per-row softmax-weighted mean: out[r] = sum_m e^{L[r,m]-max} vmean[m] / sum e
// One block (256 threads) per row.
// ---------------------------------------------------------------------------
__global__ __launch_bounds__(256)
void softmax_out_kernel(float* __restrict__ out) {
    const int r = blockIdx.x;
    const float* row = g_L + (size_t)r * N;
    const float* vm = g_vmean + (r >> 12) * N;   // batch base
    const int tid = threadIdx.x;

    __shared__ float red0[256];
    __shared__ float red1[256];

    float mx = -3.4e38f;
    for (int j = tid; j < N; j += 256) mx = fmaxf(mx, row[j]);
    red0[tid] = mx;
    __syncthreads();
    for (int s = 128; s > 0; s >>= 1) {
        if (tid < s) red0[tid] = fmaxf(red0[tid], red0[tid + s]);
        __syncthreads();
    }
    const float m = red0[0];
    __syncthreads();

    float s0 = 0.f, s1 = 0.f;
    for (int j = tid; j < N; j += 256) {
        float e = __expf(row[j] - m);
        s0 += e;
        s1 += e * vm[j];
    }
    red0[tid] = s0;
    red1[tid] = s1;
    __syncthreads();
    for (int s = 128; s > 0; s >>= 1) {
        if (tid < s) { red0[tid] += red0[tid + s]; red1[tid] += red1[tid + s]; }
        __syncthreads();
    }
    if (tid == 0) out[r] = red1[0] / red0[0];
}

// ---------------------------------------------------------------------------
extern "C" void kernel_launch(void* const* d_in, const int* in_sizes, int n_in,
                              void* d_out, int out_size) {
    const float* X  = (const float*)d_in[0];   // [4,4096,1024]
    const float* Wq = (const float*)d_in[1];   // [1024,1024]
    const float* Wk = (const float*)d_in[2];
    const float* Wv = (const float*)d_in[3];
    float* out = (float*)d_out;                // [4,4096]

    float* Qp; cudaGetSymbolAddress((void**)&Qp, g_Q);
    float* Kp; cudaGetSymbolAddress((void**)&Kp, g_K);

    // 1. wvbar: 1024 rows, 8 warps/block
    wvbar_kernel<<<D / 8, 256>>>(Wv);

    // 2. vmean: 16384 rows, 8 warps/block
    vmean_kernel<<<ROWS / 8, 256>>>(X);

    // 3. Q = X @ Wq, 4. K = X @ Wk
    {
        dim3 grid(D / BN, ROWS / BM);
        sgemm_nn<<<grid, 256>>>(X, Wq, Qp, ROWS, D, D);
        sgemm_nn<<<grid, 256>>>(X, Wk, Kp, ROWS, D, D);
    }

    // 5. logits (batched NT)
    {
        dim3 grid(N / BN, N / BM, B);
        logits_nt<<<grid, 256>>>();
    }

    // 6. softmax-weighted mean -> out
    softmax_out_kernel<<<ROWS, 256>>>(out);
}

// round 3
// speedup vs baseline: 2.4068x; 2.4068x over previous
#include <cuda_runtime.h>
#include <cuda_bf16.h>
#include <cstdint>

#define BATCH 4
#define SEQ   4096
#define EMB   1024
#define ROWS  (BATCH * SEQ)      // 16384
#define SCALE 0.03125f           // 1/sqrt(1024)

// GEMM tiling
#define CTM 128
#define CTN 128
#define KSTAGE 32                // bf16 k per stage
#define NSTAGES 4
#define KSTEPS (EMB / KSTAGE)    // 32

// smem: 4 matrices (Ahi, Alo, Bhi, Blo) per stage, each 128 rows x 40 bf16 (80B stride)
#define ROWSTRIDE_B 80           // bytes
#define MAT_BYTES  (128 * ROWSTRIDE_B)   // 10240
#define STAGE_BYTES (4 * MAT_BYTES)      // 40960
#define DSMEM_BYTES (NSTAGES * STAGE_BYTES)  // 163840

// ---------------------------------------------------------------------------
// Scratch (device globals)
// ---------------------------------------------------------------------------
__device__ __nv_bfloat16 g_Xhi[(size_t)ROWS * EMB];
__device__ __nv_bfloat16 g_Xlo[(size_t)ROWS * EMB];
__device__ __nv_bfloat16 g_Wqt_hi[EMB * EMB], g_Wqt_lo[EMB * EMB];
__device__ __nv_bfloat16 g_Wkt_hi[EMB * EMB], g_Wkt_lo[EMB * EMB];
__device__ __nv_bfloat16 g_Qhi[(size_t)ROWS * EMB], g_Qlo[(size_t)ROWS * EMB];
__device__ __nv_bfloat16 g_Khi[(size_t)ROWS * EMB], g_Klo[(size_t)ROWS * EMB];
__device__ float g_L[(size_t)BATCH * SEQ * SEQ];   // 256 MB
__device__ float g_vmean[ROWS];
__device__ float g_wvbar[EMB];

// ---------------------------------------------------------------------------
// Helpers
// ---------------------------------------------------------------------------
__device__ __forceinline__ uint32_t smem_u32(const void* p) {
    uint32_t a;
    asm("{ .reg .u64 t; cvta.to.shared.u64 t, %1; cvt.u32.u64 %0, t; }" : "=r"(a) : "l"(p));
    return a;
}
__device__ __forceinline__ void cp_async16(uint32_t dst, const void* src) {
    asm volatile("cp.async.cg.shared.global [%0], [%1], 16;" :: "r"(dst), "l"(src) : "memory");
}
__device__ __forceinline__ void cp_commit() {
    asm volatile("cp.async.commit_group;" ::: "memory");
}
template <int NN>
__device__ __forceinline__ void cp_wait() {
    asm volatile("cp.async.wait_group %0;" :: "n"(NN) : "memory");
}
__device__ __forceinline__ void ldm_x4(uint32_t* r, uint32_t addr) {
    asm volatile("ldmatrix.sync.aligned.m8n8.x4.shared.b16 {%0,%1,%2,%3}, [%4];"
                 : "=r"(r[0]), "=r"(r[1]), "=r"(r[2]), "=r"(r[3]) : "r"(addr));
}
__device__ __forceinline__ void mma16816(float* c, const uint32_t* a, uint32_t b0, uint32_t b1) {
    asm volatile("mma.sync.aligned.m16n8k16.row.col.f32.bf16.bf16.f32 "
                 "{%0,%1,%2,%3}, {%4,%5,%6,%7}, {%8,%9}, {%0,%1,%2,%3};"
                 : "+f"(c[0]), "+f"(c[1]), "+f"(c[2]), "+f"(c[3])
                 : "r"(a[0]), "r"(a[1]), "r"(a[2]), "r"(a[3]), "r"(b0), "r"(b1));
}
__device__ __forceinline__ uint32_t packbf(__nv_bfloat16 a, __nv_bfloat16 b) {
    __nv_bfloat162 t = __halves2bfloat162(a, b);
    return *reinterpret_cast<uint32_t*>(&t);
}

// ---------------------------------------------------------------------------
// Prep kernels
// ---------------------------------------------------------------------------
__global__ void wvbar_kernel(const float* __restrict__ Wv) {
    int row = blockIdx.x * (blockDim.x >> 5) + (threadIdx.x >> 5);
    int lane = threadIdx.x & 31;
    if (row >= EMB) return;
    const float* p = Wv + (size_t)row * EMB;
    float s = 0.f;
    #pragma unroll 4
    for (int j = lane; j < EMB; j += 32) s += p[j];
    #pragma unroll
    for (int o = 16; o > 0; o >>= 1) s += __shfl_xor_sync(0xffffffffu, s, o);
    if (lane == 0) g_wvbar[row] = s * (1.0f / (float)EMB);
}

__global__ void vmean_kernel(const float* __restrict__ X) {
    int row = blockIdx.x * (blockDim.x >> 5) + (threadIdx.x >> 5);
    int lane = threadIdx.x & 31;
    if (row >= ROWS) return;
    const float4* p = (const float4*)(X + (size_t)row * EMB);
    const float4* w = (const float4*)g_wvbar;
    float s = 0.f;
    #pragma unroll 8
    for (int j = lane; j < EMB / 4; j += 32) {
        float4 a = p[j], b = w[j];
        s += a.x * b.x + a.y * b.y + a.z * b.z + a.w * b.w;
    }
    #pragma unroll
    for (int o = 16; o > 0; o >>= 1) s += __shfl_xor_sync(0xffffffffu, s, o);
    if (lane == 0) g_vmean[row] = s;
}

__global__ void split_kernel(const float4* __restrict__ src,
                             uint2* __restrict__ hi, uint2* __restrict__ lo, int n4) {
    int i = blockIdx.x * blockDim.x + threadIdx.x;
    if (i >= n4) return;
    float4 v = src[i];
    __nv_bfloat16 h0 = __float2bfloat16(v.x), h1 = __float2bfloat16(v.y);
    __nv_bfloat16 h2 = __float2bfloat16(v.z), h3 = __float2bfloat16(v.w);
    __nv_bfloat16 l0 = __float2bfloat16(v.x - __bfloat162float(h0));
    __nv_bfloat16 l1 = __float2bfloat16(v.y - __bfloat162float(h1));
    __nv_bfloat16 l2 = __float2bfloat16(v.z - __bfloat162float(h2));
    __nv_bfloat16 l3 = __float2bfloat16(v.w - __bfloat162float(h3));
    hi[i] = make_uint2(packbf(h0, h1), packbf(h2, h3));
    lo[i] = make_uint2(packbf(l0, l1), packbf(l2, l3));
}

__global__ void transpose_split_kernel(const float* __restrict__ W,
                                       __nv_bfloat16* __restrict__ hi,
                                       __nv_bfloat16* __restrict__ lo) {
    __shared__ float t[32][33];
    int bx = blockIdx.x * 32, by = blockIdx.y * 32;
    int tx = threadIdx.x, ty = threadIdx.y;   // 32x8
    #pragma unroll
    for (int j = 0; j < 32; j += 8)
        t[ty + j][tx] = W[(size_t)(by + ty + j) * EMB + bx + tx];
    __syncthreads();
    #pragma unroll
    for (int j = 0; j < 32; j += 8) {
        float v = t[tx][ty + j];
        size_t o = (size_t)(bx + ty + j) * EMB + (by + tx);
        __nv_bfloat16 h = __float2bfloat16(v);
        hi[o] = h;
        lo[o] = __float2bfloat16(v - __bfloat162float(h));
    }
}

// ---------------------------------------------------------------------------
// bf16x2-split NT GEMM via mma.sync: C[M,N] = A[M,K] . B[N,K]^T, K = 1024
// mode 0: write C as split bf16 (Chi, Clo); mode 1: write fp32 * scale
// ---------------------------------------------------------------------------
__global__ __launch_bounds__(256)
void gemm_nt_mma(const __nv_bfloat16* __restrict__ Ahi, const __nv_bfloat16* __restrict__ Alo,
                 const __nv_bfloat16* __restrict__ Bhi, const __nv_bfloat16* __restrict__ Blo,
                 size_t aBatch, size_t bBatch, int mode,
                 float* __restrict__ Cf, size_t cBatch, int ldC, float scale,
                 __nv_bfloat16* __restrict__ Chi, __nv_bfloat16* __restrict__ Clo) {
    extern __shared__ char smem[];
    const uint32_t sbase = smem_u32(smem);
    const int tid = threadIdx.x;
    const int lane = tid & 31;
    const int wid = tid >> 5;
    const int wm = wid >> 2;          // 0..1
    const int wn = wid & 3;           // 0..3
    const int bz = blockIdx.z;
    const int mBase = blockIdx.y * CTM;
    const int nBase = blockIdx.x * CTN;

    const __nv_bfloat16* gsrc[4];
    gsrc[0] = Ahi + (size_t)bz * aBatch + (size_t)mBase * EMB;
    gsrc[1] = Alo + (size_t)bz * aBatch + (size_t)mBase * EMB;
    gsrc[2] = Bhi + (size_t)bz * bBatch + (size_t)nBase * EMB;
    gsrc[3] = Blo + (size_t)bz * bBatch + (size_t)nBase * EMB;

    // cp.async assignments: 2 chunks per matrix per thread
    const int ch0 = tid, ch1 = tid + 256;
    const int r0 = ch0 >> 2, s0 = ch0 & 3;
    const int r1 = ch1 >> 2, s1 = ch1 & 3;

    // ldmatrix lane offsets (bytes)
    const uint32_t aRowOff = (uint32_t)(wm * 64 + (lane & 15)) * ROWSTRIDE_B;
    const uint32_t aKsel = ((lane >> 4) & 1) * 16;
    const uint32_t bRowOff = (uint32_t)(wn * 32 + ((lane >> 4) & 1) * 8 + (lane & 7)) * ROWSTRIDE_B;
    const uint32_t bKsel = ((lane >> 3) & 1) * 16;

    float acc[4][4][4];
    #pragma unroll
    for (int i = 0; i < 4; i++)
        #pragma unroll
        for (int j = 0; j < 4; j++)
            #pragma unroll
            for (int q = 0; q < 4; q++) acc[i][j][q] = 0.f;

    auto load_stage = [&](int k0, int buf) {
        uint32_t sb = sbase + buf * STAGE_BYTES;
        #pragma unroll
        for (int m = 0; m < 4; m++) {
            const __nv_bfloat16* g = gsrc[m] + k0 * KSTAGE;
            cp_async16(sb + m * MAT_BYTES + r0 * ROWSTRIDE_B + s0 * 16,
                       g + (size_t)r0 * EMB + s0 * 8);
            cp_async16(sb + m * MAT_BYTES + r1 * ROWSTRIDE_B + s1 * 16,
                       g + (size_t)r1 * EMB + s1 * 8);
        }
    };

    // prologue: stages 0..NSTAGES-2
    #pragma unroll
    for (int s = 0; s < NSTAGES - 1; s++) {
        load_stage(s, s);
        cp_commit();
    }

    for (int k0 = 0; k0 < KSTEPS; k0++) {
        cp_wait<NSTAGES - 2>();
        __syncthreads();
        if (k0 + NSTAGES - 1 < KSTEPS)
            load_stage(k0 + NSTAGES - 1, (k0 + NSTAGES - 1) % NSTAGES);
        cp_commit();

        const uint32_t sb = sbase + (k0 % NSTAGES) * STAGE_BYTES;
        #pragma unroll
        for (int kk = 0; kk < 2; kk++) {
            const uint32_t kByte = kk * 32;
            uint32_t ah[4][4], al[4][4], bh[8], bl[8];
            #pragma unroll
            for (int mt = 0; mt < 4; mt++) {
                uint32_t ao = aRowOff + (uint32_t)(mt * 16) * ROWSTRIDE_B + kByte + aKsel;
                ldm_x4(ah[mt], sb + 0 * MAT_BYTES + ao);
                ldm_x4(al[mt], sb + 1 * MAT_BYTES + ao);
            }
            #pragma unroll
            for (int p = 0; p < 2; p++) {
                uint32_t bo = bRowOff + (uint32_t)(p * 16) * ROWSTRIDE_B + kByte + bKsel;
                ldm_x4(&bh[p * 4], sb + 2 * MAT_BYTES + bo);
                ldm_x4(&bl[p * 4], sb + 3 * MAT_BYTES + bo);
            }
            #pragma unroll
            for (int mt = 0; mt < 4; mt++)
                #pragma unroll
                for (int nt = 0; nt < 4; nt++) {
                    mma16816(acc[mt][nt], ah[mt], bh[nt * 2], bh[nt * 2 + 1]);
                    mma16816(acc[mt][nt], ah[mt], bl[nt * 2], bl[nt * 2 + 1]);
                    mma16816(acc[mt][nt], al[mt], bh[nt * 2], bh[nt * 2 + 1]);
                }
        }
    }
    cp_wait<0>();

    // Epilogue: direct register -> gmem
    const int mrow = mBase + wm * 64 + (lane >> 2);
    const int ncol = nBase + wn * 32 + (lane & 3) * 2;
    if (mode == 0) {
        #pragma unroll
        for (int mt = 0; mt < 4; mt++)
            #pragma unroll
            for (int nt = 0; nt < 4; nt++) {
                #pragma unroll
                for (int half = 0; half < 2; half++) {
                    float v0 = acc[mt][nt][half * 2 + 0];
                    float v1 = acc[mt][nt][half * 2 + 1];
                    __nv_bfloat16 h0 = __float2bfloat16(v0);
                    __nv_bfloat16 h1 = __float2bfloat16(v1);
                    __nv_bfloat16 l0 = __float2bfloat16(v0 - __bfloat162float(h0));
                    __nv_bfloat16 l1 = __float2bfloat16(v1 - __bfloat162float(h1));
                    size_t o = (size_t)(mrow + mt * 16 + half * 8) * EMB + (ncol + nt * 8);
                    *(uint32_t*)(Chi + o) = packbf(h0, h1);
                    *(uint32_t*)(Clo + o) = packbf(l0, l1);
                }
            }
    } else {
        float* Cp = Cf + (size_t)bz * cBatch;
        #pragma unroll
        for (int mt = 0; mt < 4; mt++)
            #pragma unroll
            for (int nt = 0; nt < 4; nt++) {
                #pragma unroll
                for (int half = 0; half < 2; half++) {
                    float2 v;
                    v.x = acc[mt][nt][half * 2 + 0] * scale;
                    v.y = acc[mt][nt][half * 2 + 1] * scale;
                    *(float2*)(Cp + (size_t)(mrow + mt * 16 + half * 8) * ldC + (ncol + nt * 8)) = v;
                }
            }
    }
}

// ---------------------------------------------------------------------------
// Softmax-weighted mean epilogue
// ---------------------------------------------------------------------------
__global__ __launch_bounds__(256)
void softmax_out_kernel(float* __restrict__ out) {
    const int r = blockIdx.x;
    const float* row = g_L + (size_t)r * SEQ;
    const float* vm = g_vmean + (r >> 12) * SEQ;
    const int tid = threadIdx.x;

    __shared__ float red0[256];
    __shared__ float red1[256];

    float mx = -3.4e38f;
    for (int j = tid; j < SEQ; j += 256) mx = fmaxf(mx, row[j]);
    red0[tid] = mx;
    __syncthreads();
    for (int s = 128; s > 0; s >>= 1) {
        if (tid < s) red0[tid] = fmaxf(red0[tid], red0[tid + s]);
        __syncthreads();
    }
    const float m = red0[0];
    __syncthreads();

    float s0 = 0.f, s1 = 0.f;
    for (int j = tid; j < SEQ; j += 256) {
        float e = __expf(row[j] - m);
        s0 += e;
        s1 += e * vm[j];
    }
    red0[tid] = s0;
    red1[tid] = s1;
    __syncthreads();
    for (int s = 128; s > 0; s >>= 1) {
        if (tid < s) { red0[tid] += red0[tid + s]; red1[tid] += red1[tid + s]; }
        __syncthreads();
    }
    if (tid == 0) out[r] = red1[0] / red0[0];
}

// ---------------------------------------------------------------------------
extern "C" void kernel_launch(void* const* d_in, const int* in_sizes, int n_in,
                              void* d_out, int out_size) {
    const float* X  = (const float*)d_in[0];
    const float* Wq = (const float*)d_in[1];
    const float* Wk = (const float*)d_in[2];
    const float* Wv = (const float*)d_in[3];
    float* out = (float*)d_out;

    __nv_bfloat16 *Xhi, *Xlo, *Wqh, *Wql, *Wkh, *Wkl, *Qh, *Ql, *Kh, *Kl;
    float *Lp;
    cudaGetSymbolAddress((void**)&Xhi, g_Xhi);
    cudaGetSymbolAddress((void**)&Xlo, g_Xlo);
    cudaGetSymbolAddress((void**)&Wqh, g_Wqt_hi);
    cudaGetSymbolAddress((void**)&Wql, g_Wqt_lo);
    cudaGetSymbolAddress((void**)&Wkh, g_Wkt_hi);
    cudaGetSymbolAddress((void**)&Wkl, g_Wkt_lo);
    cudaGetSymbolAddress((void**)&Qh, g_Qhi);
    cudaGetSymbolAddress((void**)&Ql, g_Qlo);
    cudaGetSymbolAddress((void**)&Kh, g_Khi);
    cudaGetSymbolAddress((void**)&Kl, g_Klo);
    cudaGetSymbolAddress((void**)&Lp, g_L);

    cudaFuncSetAttribute(gemm_nt_mma, cudaFuncAttributeMaxDynamicSharedMemorySize, DSMEM_BYTES);

    // Prep
    wvbar_kernel<<<EMB / 8, 256>>>(Wv);
    vmean_kernel<<<ROWS / 8, 256>>>(X);
    {
        int n4 = ROWS * EMB / 4;
        split_kernel<<<n4 / 256, 256>>>((const float4*)X, (uint2*)Xhi, (uint2*)Xlo, n4);
        dim3 blk(32, 8), grd(EMB / 32, EMB / 32);
        transpose_split_kernel<<<grd, blk>>>(Wq, Wqh, Wql);
        transpose_split_kernel<<<grd, blk>>>(Wk, Wkh, Wkl);
    }

    // Q = X @ Wq, K = X @ Wk (NT against transposed W), split-bf16 outputs
    {
        dim3 grid(EMB / CTN, ROWS / CTM, 1);
        gemm_nt_mma<<<grid, 256, DSMEM_BYTES>>>(Xhi, Xlo, Wqh, Wql, 0, 0,
                                                0, nullptr, 0, 0, 1.0f, Qh, Ql);
        gemm_nt_mma<<<grid, 256, DSMEM_BYTES>>>(Xhi, Xlo, Wkh, Wkl, 0, 0,
                                                0, nullptr, 0, 0, 1.0f, Kh, Kl);
    }

    // logits = scale * Q @ K^T (batched)
    {
        dim3 grid(SEQ / CTN, SEQ / CTM, BATCH);
        gemm_nt_mma<<<grid, 256, DSMEM_BYTES>>>(Qh, Ql, Kh, Kl,
                                                (size_t)SEQ * EMB, (size_t)SEQ * EMB,
                                                1, Lp, (size_t)SEQ * SEQ, SEQ, SCALE,
                                                nullptr, nullptr);
    }

    // softmax-weighted mean
    softmax_out_kernel<<<ROWS, 256>>>(out);
}

// round 4
// speedup vs baseline: 2.4615x; 1.0228x over previous
#include <cuda_runtime.h>
#include <cuda_bf16.h>
#include <cstdint>

#define BATCH 4
#define SEQ   4096
#define EMB   1024
#define ROWS  (BATCH * SEQ)      // 16384
#define SCALE 0.03125f           // 1/sqrt(1024)

// GEMM tiling
#define CTM 128
#define CTN 128
#define KSTAGE 32                // bf16 k per stage
#define NSTAGES 4
#define KSTEPS (EMB / KSTAGE)    // 32

#define ROWSTRIDE_B 80           // bytes (32 bf16 + pad)
#define MAT_BYTES  (128 * ROWSTRIDE_B)       // 10240
#define STAGE_BYTES (4 * MAT_BYTES)          // 40960
#define DSMEM_BYTES (NSTAGES * STAGE_BYTES)  // 163840

// ---------------------------------------------------------------------------
// Scratch (device globals)
// ---------------------------------------------------------------------------
__device__ __nv_bfloat16 g_Xhi[(size_t)ROWS * EMB];
__device__ __nv_bfloat16 g_Xlo[(size_t)ROWS * EMB];
__device__ __nv_bfloat16 g_Wqt_hi[EMB * EMB], g_Wqt_lo[EMB * EMB];
__device__ __nv_bfloat16 g_Wkt_hi[EMB * EMB], g_Wkt_lo[EMB * EMB];
__device__ __nv_bfloat16 g_Qhi[(size_t)ROWS * EMB], g_Qlo[(size_t)ROWS * EMB];
__device__ __nv_bfloat16 g_Khi[(size_t)ROWS * EMB], g_Klo[(size_t)ROWS * EMB];
__device__ float g_L[(size_t)BATCH * SEQ * SEQ];   // 256 MB
__device__ float g_vmean[ROWS];
__device__ float g_wvbar[EMB];
__device__ unsigned int g_rowmax[ROWS];            // order-preserving float encoding

// ---------------------------------------------------------------------------
// Helpers
// ---------------------------------------------------------------------------
__device__ __forceinline__ uint32_t smem_u32(const void* p) {
    uint32_t a;
    asm("{ .reg .u64 t; cvta.to.shared.u64 t, %1; cvt.u32.u64 %0, t; }" : "=r"(a) : "l"(p));
    return a;
}
__device__ __forceinline__ void cp_async16(uint32_t dst, const void* src) {
    asm volatile("cp.async.cg.shared.global [%0], [%1], 16;" :: "r"(dst), "l"(src) : "memory");
}
__device__ __forceinline__ void cp_commit() {
    asm volatile("cp.async.commit_group;" ::: "memory");
}
template <int NN>
__device__ __forceinline__ void cp_wait() {
    asm volatile("cp.async.wait_group %0;" :: "n"(NN) : "memory");
}
__device__ __forceinline__ void ldm_x4(uint32_t* r, uint32_t addr) {
    asm volatile("ldmatrix.sync.aligned.m8n8.x4.shared.b16 {%0,%1,%2,%3}, [%4];"
                 : "=r"(r[0]), "=r"(r[1]), "=r"(r[2]), "=r"(r[3]) : "r"(addr));
}
__device__ __forceinline__ void mma16816(float* c, const uint32_t* a, uint32_t b0, uint32_t b1) {
    asm volatile("mma.sync.aligned.m16n8k16.row.col.f32.bf16.bf16.f32 "
                 "{%0,%1,%2,%3}, {%4,%5,%6,%7}, {%8,%9}, {%0,%1,%2,%3};"
                 : "+f"(c[0]), "+f"(c[1]), "+f"(c[2]), "+f"(c[3])
                 : "r"(a[0]), "r"(a[1]), "r"(a[2]), "r"(a[3]), "r"(b0), "r"(b1));
}
__device__ __forceinline__ uint32_t packbf(__nv_bfloat16 a, __nv_bfloat16 b) {
    __nv_bfloat162 t = __halves2bfloat162(a, b);
    return *reinterpret_cast<uint32_t*>(&t);
}
// order-preserving float<->uint for atomicMax
__device__ __forceinline__ unsigned int fenc(float f) {
    unsigned int b = __float_as_uint(f);
    return (b & 0x80000000u) ? ~b : (b | 0x80000000u);
}
__device__ __forceinline__ float fdec(unsigned int u) {
    unsigned int b = (u & 0x80000000u) ? (u & 0x7FFFFFFFu) : ~u;
    return __uint_as_float(b);
}

// ---------------------------------------------------------------------------
// prep1: range-branched mega-kernel (256 threads/block, 1D grid)
//   [0, 16384)          : split X -> Xhi/Xlo (256 float4 per block)
//   [16384, 17408)      : transpose+split Wq
//   [17408, 18432)      : transpose+split Wk
//   [18432, 18560)      : wvbar (8 rows per block)
//   [18560, 18624)      : rowmax init
// ---------------------------------------------------------------------------
#define P_SPLIT_END 16384
#define P_TQ_END    17408
#define P_TK_END    18432
#define P_WV_END    18560
#define P_RM_END    18624

__device__ __forceinline__ void do_transpose_split(const float* __restrict__ W,
                                                   __nv_bfloat16* __restrict__ hi,
                                                   __nv_bfloat16* __restrict__ lo,
                                                   int bi) {
    __shared__ float t[32][33];
    int bx = (bi & 31) * 32, by = (bi >> 5) * 32;
    int tx = threadIdx.x & 31, ty = threadIdx.x >> 5;   // 32x8
    #pragma unroll
    for (int j = 0; j < 32; j += 8)
        t[ty + j][tx] = W[(size_t)(by + ty + j) * EMB + bx + tx];
    __syncthreads();
    #pragma unroll
    for (int j = 0; j < 32; j += 8) {
        float v = t[tx][ty + j];
        size_t o = (size_t)(bx + ty + j) * EMB + (by + tx);
        __nv_bfloat16 h = __float2bfloat16(v);
        hi[o] = h;
        lo[o] = __float2bfloat16(v - __bfloat162float(h));
    }
}

__global__ __launch_bounds__(256)
void prep1_kernel(const float* __restrict__ X,
                  const float* __restrict__ Wq,
                  const float* __restrict__ Wk,
                  const float* __restrict__ Wv) {
    const int b = blockIdx.x;
    if (b < P_SPLIT_END) {
        int i = b * 256 + threadIdx.x;             // float4 index
        float4 v = ((const float4*)X)[i];
        __nv_bfloat16 h0 = __float2bfloat16(v.x), h1 = __float2bfloat16(v.y);
        __nv_bfloat16 h2 = __float2bfloat16(v.z), h3 = __float2bfloat16(v.w);
        __nv_bfloat16 l0 = __float2bfloat16(v.x - __bfloat162float(h0));
        __nv_bfloat16 l1 = __float2bfloat16(v.y - __bfloat162float(h1));
        __nv_bfloat16 l2 = __float2bfloat16(v.z - __bfloat162float(h2));
        __nv_bfloat16 l3 = __float2bfloat16(v.w - __bfloat162float(h3));
        ((uint2*)g_Xhi)[i] = make_uint2(packbf(h0, h1), packbf(h2, h3));
        ((uint2*)g_Xlo)[i] = make_uint2(packbf(l0, l1), packbf(l2, l3));
    } else if (b < P_TQ_END) {
        do_transpose_split(Wq, g_Wqt_hi, g_Wqt_lo, b - P_SPLIT_END);
    } else if (b < P_TK_END) {
        do_transpose_split(Wk, g_Wkt_hi, g_Wkt_lo, b - P_TQ_END);
    } else if (b < P_WV_END) {
        int row = (b - P_TK_END) * 8 + (threadIdx.x >> 5);
        int lane = threadIdx.x & 31;
        const float* p = Wv + (size_t)row * EMB;
        float s = 0.f;
        #pragma unroll 4
        for (int j = lane; j < EMB; j += 32) s += p[j];
        #pragma unroll
        for (int o = 16; o > 0; o >>= 1) s += __shfl_xor_sync(0xffffffffu, s, o);
        if (lane == 0) g_wvbar[row] = s * (1.0f / (float)EMB);
    } else {
        int i = (b - P_WV_END) * 256 + threadIdx.x;
        g_rowmax[i] = 0u;   // bottom of order-preserving encoding
    }
}

__global__ void vmean_kernel(const float* __restrict__ X) {
    int row = blockIdx.x * (blockDim.x >> 5) + (threadIdx.x >> 5);
    int lane = threadIdx.x & 31;
    if (row >= ROWS) return;
    const float4* p = (const float4*)(X + (size_t)row * EMB);
    const float4* w = (const float4*)g_wvbar;
    float s = 0.f;
    #pragma unroll 8
    for (int j = lane; j < EMB / 4; j += 32) {
        float4 a = p[j], b = w[j];
        s += a.x * b.x + a.y * b.y + a.z * b.z + a.w * b.w;
    }
    #pragma unroll
    for (int o = 16; o > 0; o >>= 1) s += __shfl_xor_sync(0xffffffffu, s, o);
    if (lane == 0) g_vmean[row] = s;
}

// ---------------------------------------------------------------------------
// bf16x2-split NT GEMM via mma.sync: C[M,N] = A[M,K] . B[N,K]^T, K = 1024
// Pass-major MMA ordering (hh / hl / lh) to break acc RAW chains.
// mode 0: write C as split bf16 (Chi, Clo); mode 1: write fp32*scale + rowmax
// ---------------------------------------------------------------------------
__global__ __launch_bounds__(256)
void gemm_nt_mma(const __nv_bfloat16* __restrict__ Ahi, const __nv_bfloat16* __restrict__ Alo,
                 const __nv_bfloat16* __restrict__ Bhi, const __nv_bfloat16* __restrict__ Blo,
                 size_t aBatch, size_t bBatch, int mode,
                 float* __restrict__ Cf, size_t cBatch, int ldC, float scale,
                 __nv_bfloat16* __restrict__ Chi, __nv_bfloat16* __restrict__ Clo) {
    extern __shared__ char smem[];
    const uint32_t sbase = smem_u32(smem);
    const int tid = threadIdx.x;
    const int lane = tid & 31;
    const int wid = tid >> 5;
    const int wm = wid >> 2;          // 0..1
    const int wn = wid & 3;           // 0..3
    const int bz = blockIdx.z;
    const int mBase = blockIdx.y * CTM;
    const int nBase = blockIdx.x * CTN;

    const __nv_bfloat16* gsrc[4];
    gsrc[0] = Ahi + (size_t)bz * aBatch + (size_t)mBase * EMB;
    gsrc[1] = Alo + (size_t)bz * aBatch + (size_t)mBase * EMB;
    gsrc[2] = Bhi + (size_t)bz * bBatch + (size_t)nBase * EMB;
    gsrc[3] = Blo + (size_t)bz * bBatch + (size_t)nBase * EMB;

    const int ch0 = tid, ch1 = tid + 256;
    const int r0 = ch0 >> 2, s0 = ch0 & 3;
    const int r1 = ch1 >> 2, s1 = ch1 & 3;

    const uint32_t aRowOff = (uint32_t)(wm * 64 + (lane & 15)) * ROWSTRIDE_B;
    const uint32_t aKsel = ((lane >> 4) & 1) * 16;
    const uint32_t bRowOff = (uint32_t)(wn * 32 + ((lane >> 4) & 1) * 8 + (lane & 7)) * ROWSTRIDE_B;
    const uint32_t bKsel = ((lane >> 3) & 1) * 16;

    float acc[4][4][4];
    #pragma unroll
    for (int i = 0; i < 4; i++)
        #pragma unroll
        for (int j = 0; j < 4; j++)
            #pragma unroll
            for (int q = 0; q < 4; q++) acc[i][j][q] = 0.f;

    auto load_stage = [&](int k0, int buf) {
        uint32_t sb = sbase + buf * STAGE_BYTES;
        #pragma unroll
        for (int m = 0; m < 4; m++) {
            const __nv_bfloat16* g = gsrc[m] + k0 * KSTAGE;
            cp_async16(sb + m * MAT_BYTES + r0 * ROWSTRIDE_B + s0 * 16,
                       g + (size_t)r0 * EMB + s0 * 8);
            cp_async16(sb + m * MAT_BYTES + r1 * ROWSTRIDE_B + s1 * 16,
                       g + (size_t)r1 * EMB + s1 * 8);
        }
    };

    #pragma unroll
    for (int s = 0; s < NSTAGES - 1; s++) {
        load_stage(s, s);
        cp_commit();
    }

    for (int k0 = 0; k0 < KSTEPS; k0++) {
        cp_wait<NSTAGES - 2>();
        __syncthreads();
        if (k0 + NSTAGES - 1 < KSTEPS)
            load_stage(k0 + NSTAGES - 1, (k0 + NSTAGES - 1) % NSTAGES);
        cp_commit();

        const uint32_t sb = sbase + (k0 % NSTAGES) * STAGE_BYTES;
        #pragma unroll
        for (int kk = 0; kk < 2; kk++) {
            const uint32_t kByte = kk * 32;
            uint32_t ah[4][4], al[4][4], bh[8], bl[8];
            #pragma unroll
            for (int mt = 0; mt < 4; mt++) {
                uint32_t ao = aRowOff + (uint32_t)(mt * 16) * ROWSTRIDE_B + kByte + aKsel;
                ldm_x4(ah[mt], sb + 0 * MAT_BYTES + ao);
                ldm_x4(al[mt], sb + 1 * MAT_BYTES + ao);
            }
            #pragma unroll
            for (int p = 0; p < 2; p++) {
                uint32_t bo = bRowOff + (uint32_t)(p * 16) * ROWSTRIDE_B + kByte + bKsel;
                ldm_x4(&bh[p * 4], sb + 2 * MAT_BYTES + bo);
                ldm_x4(&bl[p * 4], sb + 3 * MAT_BYTES + bo);
            }
            // Pass-major: 16 independent accumulators per pass -> no RAW chains
            #pragma unroll
            for (int mt = 0; mt < 4; mt++)
                #pragma unroll
                for (int nt = 0; nt < 4; nt++)
                    mma16816(acc[mt][nt], ah[mt], bh[nt * 2], bh[nt * 2 + 1]);
            #pragma unroll
            for (int mt = 0; mt < 4; mt++)
                #pragma unroll
                for (int nt = 0; nt < 4; nt++)
                    mma16816(acc[mt][nt], ah[mt], bl[nt * 2], bl[nt * 2 + 1]);
            #pragma unroll
            for (int mt = 0; mt < 4; mt++)
                #pragma unroll
                for (int nt = 0; nt < 4; nt++)
                    mma16816(acc[mt][nt], al[mt], bh[nt * 2], bh[nt * 2 + 1]);
        }
    }
    cp_wait<0>();

    const int mrow = mBase + wm * 64 + (lane >> 2);
    const int ncol = nBase + wn * 32 + (lane & 3) * 2;
    if (mode == 0) {
        #pragma unroll
        for (int mt = 0; mt < 4; mt++)
            #pragma unroll
            for (int nt = 0; nt < 4; nt++) {
                #pragma unroll
                for (int half = 0; half < 2; half++) {
                    float v0 = acc[mt][nt][half * 2 + 0];
                    float v1 = acc[mt][nt][half * 2 + 1];
                    __nv_bfloat16 h0 = __float2bfloat16(v0);
                    __nv_bfloat16 h1 = __float2bfloat16(v1);
                    __nv_bfloat16 l0 = __float2bfloat16(v0 - __bfloat162float(h0));
                    __nv_bfloat16 l1 = __float2bfloat16(v1 - __bfloat162float(h1));
                    size_t o = (size_t)(mrow + mt * 16 + half * 8) * EMB + (ncol + nt * 8);
                    *(uint32_t*)(Chi + o) = packbf(h0, h1);
                    *(uint32_t*)(Clo + o) = packbf(l0, l1);
                }
            }
    } else {
        float* Cp = Cf + (size_t)bz * cBatch;
        #pragma unroll
        for (int mt = 0; mt < 4; mt++) {
            #pragma unroll
            for (int half = 0; half < 2; half++) {
                float rmax = -3.4e38f;
                #pragma unroll
                for (int nt = 0; nt < 4; nt++) {
                    float2 v;
                    v.x = acc[mt][nt][half * 2 + 0] * scale;
                    v.y = acc[mt][nt][half * 2 + 1] * scale;
                    rmax = fmaxf(rmax, fmaxf(v.x, v.y));
                    *(float2*)(Cp + (size_t)(mrow + mt * 16 + half * 8) * ldC + (ncol + nt * 8)) = v;
                }
                // quad (lanes sharing the row) max reduce
                rmax = fmaxf(rmax, __shfl_xor_sync(0xffffffffu, rmax, 1));
                rmax = fmaxf(rmax, __shfl_xor_sync(0xffffffffu, rmax, 2));
                if ((lane & 3) == 0) {
                    int grow = bz * SEQ + mrow + mt * 16 + half * 8;
                    atomicMax(&g_rowmax[grow], fenc(rmax));
                }
            }
        }
    }
}

// ---------------------------------------------------------------------------
// Single-pass softmax-weighted mean (uses precomputed row max)
// ---------------------------------------------------------------------------
__global__ __launch_bounds__(256)
void softmax_out_kernel(float* __restrict__ out) {
    const int r = blockIdx.x;
    const float* row = g_L + (size_t)r * SEQ;
    const float* vm = g_vmean + (r >> 12) * SEQ;
    const int tid = threadIdx.x;
    const float m = fdec(g_rowmax[r]);

    __shared__ float red0[256];
    __shared__ float red1[256];

    float s0 = 0.f, s1 = 0.f;
    for (int j = tid; j < SEQ; j += 256) {
        float e = __expf(row[j] - m);
        s0 += e;
        s1 += e * vm[j];
    }
    red0[tid] = s0;
    red1[tid] = s1;
    __syncthreads();
    for (int s = 128; s > 0; s >>= 1) {
        if (tid < s) { red0[tid] += red0[tid + s]; red1[tid] += red1[tid + s]; }
        __syncthreads();
    }
    if (tid == 0) out[r] = red1[0] / red0[0];
}

// ---------------------------------------------------------------------------
extern "C" void kernel_launch(void* const* d_in, const int* in_sizes, int n_in,
                              void* d_out, int out_size) {
    const float* X  = (const float*)d_in[0];
    const float* Wq = (const float*)d_in[1];
    const float* Wk = (const float*)d_in[2];
    const float* Wv = (const float*)d_in[3];
    float* out = (float*)d_out;

    __nv_bfloat16 *Xhi, *Xlo, *Wqh, *Wql, *Wkh, *Wkl, *Qh, *Ql, *Kh, *Kl;
    float *Lp;
    cudaGetSymbolAddress((void**)&Xhi, g_Xhi);
    cudaGetSymbolAddress((void**)&Xlo, g_Xlo);
    cudaGetSymbolAddress((void**)&Wqh, g_Wqt_hi);
    cudaGetSymbolAddress((void**)&Wql, g_Wqt_lo);
    cudaGetSymbolAddress((void**)&Wkh, g_Wkt_hi);
    cudaGetSymbolAddress((void**)&Wkl, g_Wkt_lo);
    cudaGetSymbolAddress((void**)&Qh, g_Qhi);
    cudaGetSymbolAddress((void**)&Ql, g_Qlo);
    cudaGetSymbolAddress((void**)&Kh, g_Khi);
    cudaGetSymbolAddress((void**)&Kl, g_Klo);
    cudaGetSymbolAddress((void**)&Lp, g_L);

    cudaFuncSetAttribute(gemm_nt_mma, cudaFuncAttributeMaxDynamicSharedMemorySize, DSMEM_BYTES);

    // 1. prep (split X, transpose+split Wq/Wk, wvbar, rowmax init)
    prep1_kernel<<<P_RM_END, 256>>>(X, Wq, Wk, Wv);
    // 2. vmean (needs wvbar)
    vmean_kernel<<<ROWS / 8, 256>>>(X);

    // 3-4. Q = X @ Wq, K = X @ Wk
    {
        dim3 grid(EMB / CTN, ROWS / CTM, 1);
        gemm_nt_mma<<<grid, 256, DSMEM_BYTES>>>(Xhi, Xlo, Wqh, Wql, 0, 0,
                                                0, nullptr, 0, 0, 1.0f, Qh, Ql);
        gemm_nt_mma<<<grid, 256, DSMEM_BYTES>>>(Xhi, Xlo, Wkh, Wkl, 0, 0,
                                                0, nullptr, 0, 0, 1.0f, Kh, Kl);
    }

    // 5. logits = scale * Q @ K^T (batched) + fused row-max  [ncu target]
    {
        dim3 grid(SEQ / CTN, SEQ / CTM, BATCH);
        gemm_nt_mma<<<grid, 256, DSMEM_BYTES>>>(Qh, Ql, Kh, Kl,
                                                (size_t)SEQ * EMB, (size_t)SEQ * EMB,
                                                1, Lp, (size_t)SEQ * SEQ, SEQ, SCALE,
                                                nullptr, nullptr);
    }

    // 6. single-pass softmax-weighted mean
    softmax_out_kernel<<<ROWS, 256>>>(out);
}

// round 5
// speedup vs baseline: 2.6782x; 1.0880x over previous
#include <cuda_runtime.h>
#include <cuda_bf16.h>
#include <cstdint>

#define BATCH 4
#define SEQ   4096
#define EMB   1024
#define ROWS  (BATCH * SEQ)      // 16384
#define SCALE 0.03125f           // 1/sqrt(1024)

// GEMM tiling
#define CTM 128
#define CTN 128
#define KSTAGE 32                // bf16 k per stage
#define NSTAGES 4
#define KSTEPS (EMB / KSTAGE)    // 32
#define NTHREADS 512

#define ROWSTRIDE_B 80           // bytes (32 bf16 + pad)
#define MAT_BYTES  (128 * ROWSTRIDE_B)       // 10240
#define STAGE_BYTES (4 * MAT_BYTES)          // 40960
#define DSMEM_BYTES (NSTAGES * STAGE_BYTES)  // 163840

// ---------------------------------------------------------------------------
// Scratch (device globals)
// ---------------------------------------------------------------------------
__device__ __nv_bfloat16 g_Xhi[(size_t)ROWS * EMB];
__device__ __nv_bfloat16 g_Xlo[(size_t)ROWS * EMB];
__device__ __nv_bfloat16 g_Wqt_hi[EMB * EMB], g_Wqt_lo[EMB * EMB];
__device__ __nv_bfloat16 g_Wkt_hi[EMB * EMB], g_Wkt_lo[EMB * EMB];
__device__ __nv_bfloat16 g_Qhi[(size_t)ROWS * EMB], g_Qlo[(size_t)ROWS * EMB];
__device__ __nv_bfloat16 g_Khi[(size_t)ROWS * EMB], g_Klo[(size_t)ROWS * EMB];
__device__ float g_L[(size_t)BATCH * SEQ * SEQ];   // 256 MB
__device__ float g_vmean[ROWS];
__device__ float g_wvbar[EMB];
__device__ unsigned int g_rowmax[ROWS];

// ---------------------------------------------------------------------------
// Helpers
// ---------------------------------------------------------------------------
__device__ __forceinline__ uint32_t smem_u32(const void* p) {
    uint32_t a;
    asm("{ .reg .u64 t; cvta.to.shared.u64 t, %1; cvt.u32.u64 %0, t; }" : "=r"(a) : "l"(p));
    return a;
}
__device__ __forceinline__ void cp_async16(uint32_t dst, const void* src) {
    asm volatile("cp.async.cg.shared.global [%0], [%1], 16;" :: "r"(dst), "l"(src) : "memory");
}
__device__ __forceinline__ void cp_commit() {
    asm volatile("cp.async.commit_group;" ::: "memory");
}
template <int NN>
__device__ __forceinline__ void cp_wait() {
    asm volatile("cp.async.wait_group %0;" :: "n"(NN) : "memory");
}
__device__ __forceinline__ void ldm_x4(uint32_t* r, uint32_t addr) {
    asm volatile("ldmatrix.sync.aligned.m8n8.x4.shared.b16 {%0,%1,%2,%3}, [%4];"
                 : "=r"(r[0]), "=r"(r[1]), "=r"(r[2]), "=r"(r[3]) : "r"(addr));
}
__device__ __forceinline__ void mma16816(float* c, const uint32_t* a, uint32_t b0, uint32_t b1) {
    asm volatile("mma.sync.aligned.m16n8k16.row.col.f32.bf16.bf16.f32 "
                 "{%0,%1,%2,%3}, {%4,%5,%6,%7}, {%8,%9}, {%0,%1,%2,%3};"
                 : "+f"(c[0]), "+f"(c[1]), "+f"(c[2]), "+f"(c[3])
                 : "r"(a[0]), "r"(a[1]), "r"(a[2]), "r"(a[3]), "r"(b0), "r"(b1));
}
__device__ __forceinline__ uint32_t packbf(__nv_bfloat16 a, __nv_bfloat16 b) {
    __nv_bfloat162 t = __halves2bfloat162(a, b);
    return *reinterpret_cast<uint32_t*>(&t);
}
__device__ __forceinline__ unsigned int fenc(float f) {
    unsigned int b = __float_as_uint(f);
    return (b & 0x80000000u) ? ~b : (b | 0x80000000u);
}
__device__ __forceinline__ float fdec(unsigned int u) {
    unsigned int b = (u & 0x80000000u) ? (u & 0x7FFFFFFFu) : ~u;
    return __uint_as_float(b);
}

// ---------------------------------------------------------------------------
// prep1: range-branched mega-kernel
// ---------------------------------------------------------------------------
#define P_SPLIT_END 16384
#define P_TQ_END    17408
#define P_TK_END    18432
#define P_WV_END    18560
#define P_RM_END    18624

__device__ __forceinline__ void do_transpose_split(const float* __restrict__ W,
                                                   __nv_bfloat16* __restrict__ hi,
                                                   __nv_bfloat16* __restrict__ lo,
                                                   int bi) {
    __shared__ float t[32][33];
    int bx = (bi & 31) * 32, by = (bi >> 5) * 32;
    int tx = threadIdx.x & 31, ty = threadIdx.x >> 5;   // 32x8
    #pragma unroll
    for (int j = 0; j < 32; j += 8)
        t[ty + j][tx] = W[(size_t)(by + ty + j) * EMB + bx + tx];
    __syncthreads();
    #pragma unroll
    for (int j = 0; j < 32; j += 8) {
        float v = t[tx][ty + j];
        size_t o = (size_t)(bx + ty + j) * EMB + (by + tx);
        __nv_bfloat16 h = __float2bfloat16(v);
        hi[o] = h;
        lo[o] = __float2bfloat16(v - __bfloat162float(h));
    }
}

__global__ __launch_bounds__(256)
void prep1_kernel(const float* __restrict__ X,
                  const float* __restrict__ Wq,
                  const float* __restrict__ Wk,
                  const float* __restrict__ Wv) {
    const int b = blockIdx.x;
    if (b < P_SPLIT_END) {
        int i = b * 256 + threadIdx.x;
        float4 v = ((const float4*)X)[i];
        __nv_bfloat16 h0 = __float2bfloat16(v.x), h1 = __float2bfloat16(v.y);
        __nv_bfloat16 h2 = __float2bfloat16(v.z), h3 = __float2bfloat16(v.w);
        __nv_bfloat16 l0 = __float2bfloat16(v.x - __bfloat162float(h0));
        __nv_bfloat16 l1 = __float2bfloat16(v.y - __bfloat162float(h1));
        __nv_bfloat16 l2 = __float2bfloat16(v.z - __bfloat162float(h2));
        __nv_bfloat16 l3 = __float2bfloat16(v.w - __bfloat162float(h3));
        ((uint2*)g_Xhi)[i] = make_uint2(packbf(h0, h1), packbf(h2, h3));
        ((uint2*)g_Xlo)[i] = make_uint2(packbf(l0, l1), packbf(l2, l3));
    } else if (b < P_TQ_END) {
        do_transpose_split(Wq, g_Wqt_hi, g_Wqt_lo, b - P_SPLIT_END);
    } else if (b < P_TK_END) {
        do_transpose_split(Wk, g_Wkt_hi, g_Wkt_lo, b - P_TQ_END);
    } else if (b < P_WV_END) {
        int row = (b - P_TK_END) * 8 + (threadIdx.x >> 5);
        int lane = threadIdx.x & 31;
        const float* p = Wv + (size_t)row * EMB;
        float s = 0.f;
        #pragma unroll 4
        for (int j = lane; j < EMB; j += 32) s += p[j];
        #pragma unroll
        for (int o = 16; o > 0; o >>= 1) s += __shfl_xor_sync(0xffffffffu, s, o);
        if (lane == 0) g_wvbar[row] = s * (1.0f / (float)EMB);
    } else {
        int i = (b - P_WV_END) * 256 + threadIdx.x;
        g_rowmax[i] = 0u;
    }
}

__global__ void vmean_kernel(const float* __restrict__ X) {
    int row = blockIdx.x * (blockDim.x >> 5) + (threadIdx.x >> 5);
    int lane = threadIdx.x & 31;
    if (row >= ROWS) return;
    const float4* p = (const float4*)(X + (size_t)row * EMB);
    const float4* w = (const float4*)g_wvbar;
    float s = 0.f;
    #pragma unroll 8
    for (int j = lane; j < EMB / 4; j += 32) {
        float4 a = p[j], b = w[j];
        s += a.x * b.x + a.y * b.y + a.z * b.z + a.w * b.w;
    }
    #pragma unroll
    for (int o = 16; o > 0; o >>= 1) s += __shfl_xor_sync(0xffffffffu, s, o);
    if (lane == 0) g_vmean[row] = s;
}

// ---------------------------------------------------------------------------
// bf16x2-split NT GEMM, 512 threads, 4x4 warps, warp tile 32x32
// ---------------------------------------------------------------------------
__global__ __launch_bounds__(NTHREADS)
void gemm_nt_mma(const __nv_bfloat16* __restrict__ Ahi, const __nv_bfloat16* __restrict__ Alo,
                 const __nv_bfloat16* __restrict__ Bhi, const __nv_bfloat16* __restrict__ Blo,
                 size_t aBatch, size_t bBatch, int mode,
                 float* __restrict__ Cf, size_t cBatch, int ldC, float scale,
                 __nv_bfloat16* __restrict__ Chi, __nv_bfloat16* __restrict__ Clo) {
    extern __shared__ char smem[];
    const uint32_t sbase = smem_u32(smem);
    const int tid = threadIdx.x;
    const int lane = tid & 31;
    const int wid = tid >> 5;         // 0..15
    const int wm = wid >> 2;          // 0..3
    const int wn = wid & 3;           // 0..3
    const int bz = blockIdx.z;
    const int mBase = blockIdx.y * CTM;
    const int nBase = blockIdx.x * CTN;

    const __nv_bfloat16* gsrc[4];
    gsrc[0] = Ahi + (size_t)bz * aBatch + (size_t)mBase * EMB;
    gsrc[1] = Alo + (size_t)bz * aBatch + (size_t)mBase * EMB;
    gsrc[2] = Bhi + (size_t)bz * bBatch + (size_t)nBase * EMB;
    gsrc[3] = Blo + (size_t)bz * bBatch + (size_t)nBase * EMB;

    // one 16B chunk per matrix per thread per stage (512 chunks = 128 rows x 4)
    const int r0 = tid >> 2, s0 = tid & 3;

    const uint32_t aRowOff = (uint32_t)(wm * 32 + (lane & 15)) * ROWSTRIDE_B;
    const uint32_t aKsel = ((lane >> 4) & 1) * 16;
    const uint32_t bRowOff = (uint32_t)(wn * 32 + ((lane >> 4) & 1) * 8 + (lane & 7)) * ROWSTRIDE_B;
    const uint32_t bKsel = ((lane >> 3) & 1) * 16;

    float acc[2][4][4];
    #pragma unroll
    for (int i = 0; i < 2; i++)
        #pragma unroll
        for (int j = 0; j < 4; j++)
            #pragma unroll
            for (int q = 0; q < 4; q++) acc[i][j][q] = 0.f;

    auto load_stage = [&](int k0, int buf) {
        uint32_t sb = sbase + buf * STAGE_BYTES;
        #pragma unroll
        for (int m = 0; m < 4; m++) {
            const __nv_bfloat16* g = gsrc[m] + k0 * KSTAGE;
            cp_async16(sb + m * MAT_BYTES + r0 * ROWSTRIDE_B + s0 * 16,
                       g + (size_t)r0 * EMB + s0 * 8);
        }
    };

    #pragma unroll
    for (int s = 0; s < NSTAGES - 1; s++) {
        load_stage(s, s);
        cp_commit();
    }

    for (int k0 = 0; k0 < KSTEPS; k0++) {
        cp_wait<NSTAGES - 2>();
        __syncthreads();
        if (k0 + NSTAGES - 1 < KSTEPS)
            load_stage(k0 + NSTAGES - 1, (k0 + NSTAGES - 1) % NSTAGES);
        cp_commit();

        const uint32_t sb = sbase + (k0 % NSTAGES) * STAGE_BYTES;
        #pragma unroll
        for (int kk = 0; kk < 2; kk++) {
            const uint32_t kByte = kk * 32;
            uint32_t ah[2][4], al[2][4], bh[8], bl[8];
            #pragma unroll
            for (int mt = 0; mt < 2; mt++) {
                uint32_t ao = aRowOff + (uint32_t)(mt * 16) * ROWSTRIDE_B + kByte + aKsel;
                ldm_x4(ah[mt], sb + 0 * MAT_BYTES + ao);
                ldm_x4(al[mt], sb + 1 * MAT_BYTES + ao);
            }
            #pragma unroll
            for (int p = 0; p < 2; p++) {
                uint32_t bo = bRowOff + (uint32_t)(p * 16) * ROWSTRIDE_B + kByte + bKsel;
                ldm_x4(&bh[p * 4], sb + 2 * MAT_BYTES + bo);
                ldm_x4(&bl[p * 4], sb + 3 * MAT_BYTES + bo);
            }
            // pass-major: independent accumulators within each pass
            #pragma unroll
            for (int mt = 0; mt < 2; mt++)
                #pragma unroll
                for (int nt = 0; nt < 4; nt++)
                    mma16816(acc[mt][nt], ah[mt], bh[nt * 2], bh[nt * 2 + 1]);
            #pragma unroll
            for (int mt = 0; mt < 2; mt++)
                #pragma unroll
                for (int nt = 0; nt < 4; nt++)
                    mma16816(acc[mt][nt], ah[mt], bl[nt * 2], bl[nt * 2 + 1]);
            #pragma unroll
            for (int mt = 0; mt < 2; mt++)
                #pragma unroll
                for (int nt = 0; nt < 4; nt++)
                    mma16816(acc[mt][nt], al[mt], bh[nt * 2], bh[nt * 2 + 1]);
        }
    }
    cp_wait<0>();

    const int mrow = mBase + wm * 32 + (lane >> 2);
    const int ncol = nBase + wn * 32 + (lane & 3) * 2;
    if (mode == 0) {
        #pragma unroll
        for (int mt = 0; mt < 2; mt++)
            #pragma unroll
            for (int nt = 0; nt < 4; nt++) {
                #pragma unroll
                for (int half = 0; half < 2; half++) {
                    float v0 = acc[mt][nt][half * 2 + 0];
                    float v1 = acc[mt][nt][half * 2 + 1];
                    __nv_bfloat16 h0 = __float2bfloat16(v0);
                    __nv_bfloat16 h1 = __float2bfloat16(v1);
                    __nv_bfloat16 l0 = __float2bfloat16(v0 - __bfloat162float(h0));
                    __nv_bfloat16 l1 = __float2bfloat16(v1 - __bfloat162float(h1));
                    size_t o = (size_t)(mrow + mt * 16 + half * 8) * EMB + (ncol + nt * 8);
                    *(uint32_t*)(Chi + o) = packbf(h0, h1);
                    *(uint32_t*)(Clo + o) = packbf(l0, l1);
                }
            }
    } else {
        float* Cp = Cf + (size_t)bz * cBatch;
        #pragma unroll
        for (int mt = 0; mt < 2; mt++) {
            #pragma unroll
            for (int half = 0; half < 2; half++) {
                float rmax = -3.4e38f;
                #pragma unroll
                for (int nt = 0; nt < 4; nt++) {
                    float2 v;
                    v.x = acc[mt][nt][half * 2 + 0] * scale;
                    v.y = acc[mt][nt][half * 2 + 1] * scale;
                    rmax = fmaxf(rmax, fmaxf(v.x, v.y));
                    *(float2*)(Cp + (size_t)(mrow + mt * 16 + half * 8) * ldC + (ncol + nt * 8)) = v;
                }
                rmax = fmaxf(rmax, __shfl_xor_sync(0xffffffffu, rmax, 1));
                rmax = fmaxf(rmax, __shfl_xor_sync(0xffffffffu, rmax, 2));
                if ((lane & 3) == 0) {
                    int grow = bz * SEQ + mrow + mt * 16 + half * 8;
                    atomicMax(&g_rowmax[grow], fenc(rmax));
                }
            }
        }
    }
}

// ---------------------------------------------------------------------------
// Single-pass softmax-weighted mean (vectorized), uses precomputed row max
// ---------------------------------------------------------------------------
__global__ __launch_bounds__(256)
void softmax_out_kernel(float* __restrict__ out) {
    const int r = blockIdx.x;
    const float4* row = (const float4*)(g_L + (size_t)r * SEQ);
    const float4* vm = (const float4*)(g_vmean + (r >> 12) * SEQ);
    const int tid = threadIdx.x;
    const float m = fdec(g_rowmax[r]);

    __shared__ float red0[256];
    __shared__ float red1[256];

    float s0 = 0.f, s1 = 0.f;
    #pragma unroll
    for (int j = tid; j < SEQ / 4; j += 256) {
        float4 l = row[j];
        float4 w = vm[j];
        float e0 = __expf(l.x - m), e1 = __expf(l.y - m);
        float e2 = __expf(l.z - m), e3 = __expf(l.w - m);
        s0 += (e0 + e1) + (e2 + e3);
        s1 += e0 * w.x + e1 * w.y + e2 * w.z + e3 * w.w;
    }
    red0[tid] = s0;
    red1[tid] = s1;
    __syncthreads();
    for (int s = 128; s > 0; s >>= 1) {
        if (tid < s) { red0[tid] += red0[tid + s]; red1[tid] += red1[tid + s]; }
        __syncthreads();
    }
    if (tid == 0) out[r] = red1[0] / red0[0];
}

// ---------------------------------------------------------------------------
extern "C" void kernel_launch(void* const* d_in, const int* in_sizes, int n_in,
                              void* d_out, int out_size) {
    const float* X  = (const float*)d_in[0];
    const float* Wq = (const float*)d_in[1];
    const float* Wk = (const float*)d_in[2];
    const float* Wv = (const float*)d_in[3];
    float* out = (float*)d_out;

    __nv_bfloat16 *Xhi, *Xlo, *Wqh, *Wql, *Wkh, *Wkl, *Qh, *Ql, *Kh, *Kl;
    float *Lp;
    cudaGetSymbolAddress((void**)&Xhi, g_Xhi);
    cudaGetSymbolAddress((void**)&Xlo, g_Xlo);
    cudaGetSymbolAddress((void**)&Wqh, g_Wqt_hi);
    cudaGetSymbolAddress((void**)&Wql, g_Wqt_lo);
    cudaGetSymbolAddress((void**)&Wkh, g_Wkt_hi);
    cudaGetSymbolAddress((void**)&Wkl, g_Wkt_lo);
    cudaGetSymbolAddress((void**)&Qh, g_Qhi);
    cudaGetSymbolAddress((void**)&Ql, g_Qlo);
    cudaGetSymbolAddress((void**)&Kh, g_Khi);
    cudaGetSymbolAddress((void**)&Kl, g_Klo);
    cudaGetSymbolAddress((void**)&Lp, g_L);

    cudaFuncSetAttribute(gemm_nt_mma, cudaFuncAttributeMaxDynamicSharedMemorySize, DSMEM_BYTES);

    // 1. prep
    prep1_kernel<<<P_RM_END, 256>>>(X, Wq, Wk, Wv);
    // 2. vmean
    vmean_kernel<<<ROWS / 8, 256>>>(X);

    // 3-4. Q = X @ Wq, K = X @ Wk
    {
        dim3 grid(EMB / CTN, ROWS / CTM, 1);
        gemm_nt_mma<<<grid, NTHREADS, DSMEM_BYTES>>>(Xhi, Xlo, Wqh, Wql, 0, 0,
                                                     0, nullptr, 0, 0, 1.0f, Qh, Ql);
        gemm_nt_mma<<<grid, NTHREADS, DSMEM_BYTES>>>(Xhi, Xlo, Wkh, Wkl, 0, 0,
                                                     0, nullptr, 0, 0, 1.0f, Kh, Kl);
    }

    // 5. logits = scale * Q @ K^T + fused row-max
    {
        dim3 grid(SEQ / CTN, SEQ / CTM, BATCH);
        gemm_nt_mma<<<grid, NTHREADS, DSMEM_BYTES>>>(Qh, Ql, Kh, Kl,
                                                     (size_t)SEQ * EMB, (size_t)SEQ * EMB,
                                                     1, Lp, (size_t)SEQ * SEQ, SEQ, SCALE,
                                                     nullptr, nullptr);
    }

    // 6. single-pass softmax-weighted mean
    softmax_out_kernel<<<ROWS, 256>>>(out);
}

// round 8
// speedup vs baseline: 3.1497x; 1.1761x over previous
#include <cuda_runtime.h>
#include <cuda_bf16.h>
#include <cstdint>

#define BATCH 4
#define SEQ   4096
#define EMB   1024
#define ROWS  (BATCH * SEQ)      // 16384
#define SCALE 0.03125f           // 1/sqrt(1024)

// GEMM tiling
#define CTM 128
#define CTN 128
#define KSTAGE 32                // bf16 k per stage
#define NSTAGES 4
#define KSTEPS (EMB / KSTAGE)    // 32
#define NTHREADS 512

#define ROWSTRIDE_B 80           // bytes (32 bf16 + pad)
#define MAT_BYTES  (128 * ROWSTRIDE_B)       // 10240
#define STAGE_BYTES (4 * MAT_BYTES)          // 40960
#define DSMEM_BYTES (NSTAGES * STAGE_BYTES)  // 163840

// ---------------------------------------------------------------------------
// Scratch (device globals)
// ---------------------------------------------------------------------------
__device__ __nv_bfloat16 g_Xhi[(size_t)ROWS * EMB];
__device__ __nv_bfloat16 g_Xlo[(size_t)ROWS * EMB];
__device__ __nv_bfloat16 g_Wq_hi[EMB * EMB], g_Wq_lo[EMB * EMB];
__device__ __nv_bfloat16 g_Wk_hi[EMB * EMB], g_Wk_lo[EMB * EMB];
__device__ __nv_bfloat16 g_Mt_hi[EMB * EMB], g_Mt_lo[EMB * EMB];   // (Wk Wq^T)/32
__device__ __nv_bfloat16 g_Yhi[(size_t)ROWS * EMB], g_Ylo[(size_t)ROWS * EMB];
__device__ float g_L[(size_t)BATCH * SEQ * SEQ];   // 256 MB
__device__ float g_vmean[ROWS];
__device__ float g_wvbar[EMB];
__device__ unsigned int g_rowmax[ROWS];

// ---------------------------------------------------------------------------
// Helpers
// ---------------------------------------------------------------------------
__device__ __forceinline__ uint32_t smem_u32(const void* p) {
    uint32_t a;
    asm("{ .reg .u64 t; cvta.to.shared.u64 t, %1; cvt.u32.u64 %0, t; }" : "=r"(a) : "l"(p));
    return a;
}
__device__ __forceinline__ void cp_async16(uint32_t dst, const void* src) {
    asm volatile("cp.async.cg.shared.global [%0], [%1], 16;" :: "r"(dst), "l"(src) : "memory");
}
__device__ __forceinline__ void cp_commit() {
    asm volatile("cp.async.commit_group;" ::: "memory");
}
template <int NN>
__device__ __forceinline__ void cp_wait() {
    asm volatile("cp.async.wait_group %0;" :: "n"(NN) : "memory");
}
__device__ __forceinline__ void ldm_x4(uint32_t* r, uint32_t addr) {
    asm volatile("ldmatrix.sync.aligned.m8n8.x4.shared.b16 {%0,%1,%2,%3}, [%4];"
                 : "=r"(r[0]), "=r"(r[1]), "=r"(r[2]), "=r"(r[3]) : "r"(addr));
}
__device__ __forceinline__ void mma16816(float* c, const uint32_t* a, uint32_t b0, uint32_t b1) {
    asm volatile("mma.sync.aligned.m16n8k16.row.col.f32.bf16.bf16.f32 "
                 "{%0,%1,%2,%3}, {%4,%5,%6,%7}, {%8,%9}, {%0,%1,%2,%3};"
                 : "+f"(c[0]), "+f"(c[1]), "+f"(c[2]), "+f"(c[3])
                 : "r"(a[0]), "r"(a[1]), "r"(a[2]), "r"(a[3]), "r"(b0), "r"(b1));
}
__device__ __forceinline__ uint32_t packbf(__nv_bfloat16 a, __nv_bfloat16 b) {
    __nv_bfloat162 t = __halves2bfloat162(a, b);
    return *reinterpret_cast<uint32_t*>(&t);
}
__device__ __forceinline__ unsigned int fenc(float f) {
    unsigned int b = __float_as_uint(f);
    return (b & 0x80000000u) ? ~b : (b | 0x80000000u);
}
__device__ __forceinline__ float fdec(unsigned int u) {
    unsigned int b = (u & 0x80000000u) ? (u & 0x7FFFFFFFu) : ~u;
    return __uint_as_float(b);
}

// ---------------------------------------------------------------------------
// prep1: range-branched mega-kernel
// ---------------------------------------------------------------------------
#define P_SPLIT_END 16384
#define P_WQ_END    17408
#define P_WK_END    18432
#define P_WV_END    18560
#define P_RM_END    18624

__device__ __forceinline__ void split4(const float4* __restrict__ src,
                                       uint2* __restrict__ hi, uint2* __restrict__ lo, int i) {
    float4 v = src[i];
    __nv_bfloat16 h0 = __float2bfloat16(v.x), h1 = __float2bfloat16(v.y);
    __nv_bfloat16 h2 = __float2bfloat16(v.z), h3 = __float2bfloat16(v.w);
    __nv_bfloat16 l0 = __float2bfloat16(v.x - __bfloat162float(h0));
    __nv_bfloat16 l1 = __float2bfloat16(v.y - __bfloat162float(h1));
    __nv_bfloat16 l2 = __float2bfloat16(v.z - __bfloat162float(h2));
    __nv_bfloat16 l3 = __float2bfloat16(v.w - __bfloat162float(h3));
    hi[i] = make_uint2(packbf(h0, h1), packbf(h2, h3));
    lo[i] = make_uint2(packbf(l0, l1), packbf(l2, l3));
}

__global__ __launch_bounds__(256)
void prep1_kernel(const float* __restrict__ X,
                  const float* __restrict__ Wq,
                  const float* __restrict__ Wk,
                  const float* __restrict__ Wv) {
    const int b = blockIdx.x;
    if (b < P_SPLIT_END) {
        split4((const float4*)X, (uint2*)g_Xhi, (uint2*)g_Xlo, b * 256 + threadIdx.x);
    } else if (b < P_WQ_END) {
        split4((const float4*)Wq, (uint2*)g_Wq_hi, (uint2*)g_Wq_lo,
               (b - P_SPLIT_END) * 256 + threadIdx.x);
    } else if (b < P_WK_END) {
        split4((const float4*)Wk, (uint2*)g_Wk_hi, (uint2*)g_Wk_lo,
               (b - P_WQ_END) * 256 + threadIdx.x);
    } else if (b < P_WV_END) {
        int row = (b - P_WK_END) * 8 + (threadIdx.x >> 5);
        int lane = threadIdx.x & 31;
        const float* p = Wv + (size_t)row * EMB;
        float s = 0.f;
        #pragma unroll 4
        for (int j = lane; j < EMB; j += 32) s += p[j];
        #pragma unroll
        for (int o = 16; o > 0; o >>= 1) s += __shfl_xor_sync(0xffffffffu, s, o);
        if (lane == 0) g_wvbar[row] = s * (1.0f / (float)EMB);
    } else {
        int i = (b - P_WV_END) * 256 + threadIdx.x;
        g_rowmax[i] = 0u;
    }
}

__global__ void vmean_kernel(const float* __restrict__ X) {
    int row = blockIdx.x * (blockDim.x >> 5) + (threadIdx.x >> 5);
    int lane = threadIdx.x & 31;
    if (row >= ROWS) return;
    const float4* p = (const float4*)(X + (size_t)row * EMB);
    const float4* w = (const float4*)g_wvbar;
    float s = 0.f;
    #pragma unroll 8
    for (int j = lane; j < EMB / 4; j += 32) {
        float4 a = p[j], b = w[j];
        s += a.x * b.x + a.y * b.y + a.z * b.z + a.w * b.w;
    }
    #pragma unroll
    for (int o = 16; o > 0; o >>= 1) s += __shfl_xor_sync(0xffffffffu, s, o);
    if (lane == 0) g_vmean[row] = s;
}

// ---------------------------------------------------------------------------
// bf16x2-split NT GEMM, 512 threads, 4x4 warps, warp tile 32x32
// C[M,N] = scale * A[M,K] . B[N,K]^T
// mode 0: write C as split bf16 (scaled); mode 1: write fp32 (scaled) + rowmax
// ---------------------------------------------------------------------------
__global__ __launch_bounds__(NTHREADS)
void gemm_nt_mma(const __nv_bfloat16* __restrict__ Ahi, const __nv_bfloat16* __restrict__ Alo,
                 const __nv_bfloat16* __restrict__ Bhi, const __nv_bfloat16* __restrict__ Blo,
                 size_t aBatch, size_t bBatch, int mode,
                 float* __restrict__ Cf, size_t cBatch, int ldC, float scale,
                 __nv_bfloat16* __restrict__ Chi, __nv_bfloat16* __restrict__ Clo) {
    extern __shared__ char smem[];
    const uint32_t sbase = smem_u32(smem);
    const int tid = threadIdx.x;
    const int lane = tid & 31;
    const int wid = tid >> 5;
    const int wm = wid >> 2;          // 0..3
    const int wn = wid & 3;           // 0..3
    const int bz = blockIdx.z;
    const int mBase = blockIdx.y * CTM;
    const int nBase = blockIdx.x * CTN;

    const __nv_bfloat16* gsrc[4];
    gsrc[0] = Ahi + (size_t)bz * aBatch + (size_t)mBase * EMB;
    gsrc[1] = Alo + (size_t)bz * aBatch + (size_t)mBase * EMB;
    gsrc[2] = Bhi + (size_t)bz * bBatch + (size_t)nBase * EMB;
    gsrc[3] = Blo + (size_t)bz * bBatch + (size_t)nBase * EMB;

    const int r0 = tid >> 2, s0 = tid & 3;

    const uint32_t aRowOff = (uint32_t)(wm * 32 + (lane & 15)) * ROWSTRIDE_B;
    const uint32_t aKsel = ((lane >> 4) & 1) * 16;
    const uint32_t bRowOff = (uint32_t)(wn * 32 + ((lane >> 4) & 1) * 8 + (lane & 7)) * ROWSTRIDE_B;
    const uint32_t bKsel = ((lane >> 3) & 1) * 16;

    float acc[2][4][4];
    #pragma unroll
    for (int i = 0; i < 2; i++)
        #pragma unroll
        for (int j = 0; j < 4; j++)
            #pragma unroll
            for (int q = 0; q < 4; q++) acc[i][j][q] = 0.f;

    auto load_stage = [&](int k0, int buf) {
        uint32_t sb = sbase + buf * STAGE_BYTES;
        #pragma unroll
        for (int m = 0; m < 4; m++) {
            const __nv_bfloat16* g = gsrc[m] + k0 * KSTAGE;
            cp_async16(sb + m * MAT_BYTES + r0 * ROWSTRIDE_B + s0 * 16,
                       g + (size_t)r0 * EMB + s0 * 8);
        }
    };

    #pragma unroll
    for (int s = 0; s < NSTAGES - 1; s++) {
        load_stage(s, s);
        cp_commit();
    }

    for (int k0 = 0; k0 < KSTEPS; k0++) {
        cp_wait<NSTAGES - 2>();
        __syncthreads();
        if (k0 + NSTAGES - 1 < KSTEPS)
            load_stage(k0 + NSTAGES - 1, (k0 + NSTAGES - 1) % NSTAGES);
        cp_commit();

        const uint32_t sb = sbase + (k0 % NSTAGES) * STAGE_BYTES;
        #pragma unroll
        for (int kk = 0; kk < 2; kk++) {
            const uint32_t kByte = kk * 32;
            uint32_t ah[2][4], al[2][4], bh[8], bl[8];
            #pragma unroll
            for (int mt = 0; mt < 2; mt++) {
                uint32_t ao = aRowOff + (uint32_t)(mt * 16) * ROWSTRIDE_B + kByte + aKsel;
                ldm_x4(ah[mt], sb + 0 * MAT_BYTES + ao);
                ldm_x4(al[mt], sb + 1 * MAT_BYTES + ao);
            }
            #pragma unroll
            for (int p = 0; p < 2; p++) {
                uint32_t bo = bRowOff + (uint32_t)(p * 16) * ROWSTRIDE_B + kByte + bKsel;
                ldm_x4(&bh[p * 4], sb + 2 * MAT_BYTES + bo);
                ldm_x4(&bl[p * 4], sb + 3 * MAT_BYTES + bo);
            }
            #pragma unroll
            for (int mt = 0; mt < 2; mt++)
                #pragma unroll
                for (int nt = 0; nt < 4; nt++)
                    mma16816(acc[mt][nt], ah[mt], bh[nt * 2], bh[nt * 2 + 1]);
            #pragma unroll
            for (int mt = 0; mt < 2; mt++)
                #pragma unroll
                for (int nt = 0; nt < 4; nt++)
                    mma16816(acc[mt][nt], ah[mt], bl[nt * 2], bl[nt * 2 + 1]);
            #pragma unroll
            for (int mt = 0; mt < 2; mt++)
                #pragma unroll
                for (int nt = 0; nt < 4; nt++)
                    mma16816(acc[mt][nt], al[mt], bh[nt * 2], bh[nt * 2 + 1]);
        }
    }
    cp_wait<0>();

    const int mrow = mBase + wm * 32 + (lane >> 2);
    const int ncol = nBase + wn * 32 + (lane & 3) * 2;
    if (mode == 0) {
        #pragma unroll
        for (int mt = 0; mt < 2; mt++)
            #pragma unroll
            for (int nt = 0; nt < 4; nt++) {
                #pragma unroll
                for (int half = 0; half < 2; half++) {
                    float v0 = acc[mt][nt][half * 2 + 0] * scale;
                    float v1 = acc[mt][nt][half * 2 + 1] * scale;
                    __nv_bfloat16 h0 = __float2bfloat16(v0);
                    __nv_bfloat16 h1 = __float2bfloat16(v1);
                    __nv_bfloat16 l0 = __float2bfloat16(v0 - __bfloat162float(h0));
                    __nv_bfloat16 l1 = __float2bfloat16(v1 - __bfloat162float(h1));
                    size_t o = (size_t)(mrow + mt * 16 + half * 8) * EMB + (ncol + nt * 8);
                    *(uint32_t*)(Chi + o) = packbf(h0, h1);
                    *(uint32_t*)(Clo + o) = packbf(l0, l1);
                }
            }
    } else {
        float* Cp = Cf + (size_t)bz * cBatch;
        #pragma unroll
        for (int mt = 0; mt < 2; mt++) {
            #pragma unroll
            for (int half = 0; half < 2; half++) {
                float rmax = -3.4e38f;
                #pragma unroll
                for (int nt = 0; nt < 4; nt++) {
                    float2 v;
                    v.x = acc[mt][nt][half * 2 + 0] * scale;
                    v.y = acc[mt][nt][half * 2 + 1] * scale;
                    rmax = fmaxf(rmax, fmaxf(v.x, v.y));
                    *(float2*)(Cp + (size_t)(mrow + mt * 16 + half * 8) * ldC + (ncol + nt * 8)) = v;
                }
                rmax = fmaxf(rmax, __shfl_xor_sync(0xffffffffu, rmax, 1));
                rmax = fmaxf(rmax, __shfl_xor_sync(0xffffffffu, rmax, 2));
                if ((lane & 3) == 0) {
                    int grow = bz * SEQ + mrow + mt * 16 + half * 8;
                    atomicMax(&g_rowmax[grow], fenc(rmax));
                }
            }
        }
    }
}

// ---------------------------------------------------------------------------
// Single-pass softmax-weighted mean (vectorized), uses precomputed row max
// ---------------------------------------------------------------------------
__global__ __launch_bounds__(256)
void softmax_out_kernel(float* __restrict__ out) {
    const int r = blockIdx.x;
    const float4* row = (const float4*)(g_L + (size_t)r * SEQ);
    const float4* vm = (const float4*)(g_vmean + (r >> 12) * SEQ);
    const int tid = threadIdx.x;
    const float m = fdec(g_rowmax[r]);

    __shared__ float red0[256];
    __shared__ float red1[256];

    float s0 = 0.f, s1 = 0.f;
    #pragma unroll
    for (int j = tid; j < SEQ / 4; j += 256) {
        float4 l = row[j];
        float4 w = vm[j];
        float e0 = __expf(l.x - m), e1 = __expf(l.y - m);
        float e2 = __expf(l.z - m), e3 = __expf(l.w - m);
        s0 += (e0 + e1) + (e2 + e3);
        s1 += e0 * w.x + e1 * w.y + e2 * w.z + e3 * w.w;
    }
    red0[tid] = s0;
    red1[tid] = s1;
    __syncthreads();
    for (int s = 128; s > 0; s >>= 1) {
        if (tid < s) { red0[tid] += red0[tid + s]; red1[tid] += red1[tid + s]; }
        __syncthreads();
    }
    if (tid == 0) out[r] = red1[0] / red0[0];
}

// ---------------------------------------------------------------------------
extern "C" void kernel_launch(void* const* d_in, const int* in_sizes, int n_in,
                              void* d_out, int out_size) {
    const float* X  = (const float*)d_in[0];
    const float* Wq = (const float*)d_in[1];
    const float* Wk = (const float*)d_in[2];
    const float* Wv = (const float*)d_in[3];
    float* out = (float*)d_out;

    __nv_bfloat16 *Xhi, *Xlo, *Wqh, *Wql, *Wkh, *Wkl, *Mth, *Mtl, *Yh, *Yl;
    float *Lp;
    cudaGetSymbolAddress((void**)&Xhi, g_Xhi);
    cudaGetSymbolAddress((void**)&Xlo, g_Xlo);
    cudaGetSymbolAddress((void**)&Wqh, g_Wq_hi);
    cudaGetSymbolAddress((void**)&Wql, g_Wq_lo);
    cudaGetSymbolAddress((void**)&Wkh, g_Wk_hi);
    cudaGetSymbolAddress((void**)&Wkl, g_Wk_lo);
    cudaGetSymbolAddress((void**)&Mth, g_Mt_hi);
    cudaGetSymbolAddress((void**)&Mtl, g_Mt_lo);
    cudaGetSymbolAddress((void**)&Yh, g_Yhi);
    cudaGetSymbolAddress((void**)&Yl, g_Ylo);
    cudaGetSymbolAddress((void**)&Lp, g_L);

    cudaFuncSetAttribute(gemm_nt_mma, cudaFuncAttributeMaxDynamicSharedMemorySize, DSMEM_BYTES);

    // 1. prep (split X, Wq, Wk elementwise; wvbar; rowmax init)
    prep1_kernel<<<P_RM_END, 256>>>(X, Wq, Wk, Wv);
    // 2. vmean
    vmean_kernel<<<ROWS / 8, 256>>>(X);

    // 3. Mt = (Wk . Wq^T) / 32  -> split bf16   [1024 x 1024]
    {
        dim3 grid(EMB / CTN, EMB / CTM, 1);
        gemm_nt_mma<<<grid, NTHREADS, DSMEM_BYTES>>>(Wkh, Wkl, Wqh, Wql, 0, 0,
                                                     0, nullptr, 0, 0, SCALE, Mth, Mtl);
    }

    // 4. Y = X . Mt^T -> split bf16   [16384 x 1024]   (replaces Q and K GEMMs)
    {
        dim3 grid(EMB / CTN, ROWS / CTM, 1);
        gemm_nt_mma<<<grid, NTHREADS, DSMEM_BYTES>>>(Xhi, Xlo, Mth, Mtl, 0, 0,
                                                     0, nullptr, 0, 0, 1.0f, Yh, Yl);
    }

    // 5. logits = Y . X^T (batched) + fused row-max
    {
        dim3 grid(SEQ / CTN, SEQ / CTM, BATCH);
        gemm_nt_mma<<<grid, NTHREADS, DSMEM_BYTES>>>(Yh, Yl, Xhi, Xlo,
                                                     (size_t)SEQ * EMB, (size_t)SEQ * EMB,
                                                     1, Lp, (size_t)SEQ * SEQ, SEQ, 1.0f,
                                                     nullptr, nullptr);
    }

    // 6. single-pass softmax-weighted mean
    softmax_out_kernel<<<ROWS, 256>>>(out);
}